// round 14
// baseline (speedup 1.0000x reference)
#include <cuda_runtime.h>
#include <cuda_fp16.h>
#include <math.h>
#include <cstdint>

#define NTOT   160000
#define NNODE  5000
#define NEDGE  80000
#define TSTEPS 12
#define HD     128
#define HORZ   12
#define INF    2

#define EKP 152   // half stride for extended K=144 tiles
#define NCORR 40  // blocks 0..39 own rows 0..5119 + graph prop

// ---------------- static device scratch ----------------
__device__ float g_h   [NTOT * HD];
__device__ float g_P1  [NNODE * HD];
__device__ float g_P2  [NNODE * HD];
__device__ float g_X1  [NNODE * INF];
__device__ float g_X2  [NNODE * INF];
__device__ float g_norm[NEDGE];
__device__ int   g_degsrc[NNODE];
__device__ int   g_cnt [NNODE];
__device__ int   g_off [NNODE + 1];
__device__ int   g_cur [NNODE];
__device__ int   g_csrsrc[NEDGE];
__device__ float g_csrw  [NEDGE];
__device__ float g_M6zr  [6 * 2 * HD];
__device__ float g_biaszr[2 * HD];
__device__ float g_M6c   [6 * HD];
__device__ float g_biasc [HD];
__device__ int   g_bad64;
__device__ int   g_is64;
__device__ int   g_bar;    // 40-block barrier counter (reset each replay)

// extended fp16 B tiles [n][144]: 0:A2eff(+b2) 1:W2[1] 2:2*W2[2] 3:Wz+M6z+bias 4:Wr+M6r+bias 5:Wc+M6c+bias
__device__ __align__(16) __half g_Bext[6][128 * 144];

// ---------------- warp-MMA primitives ----------------
__device__ __forceinline__ uint32_t smem_u32(const void* p) {
    uint32_t a;
    asm("{ .reg .u64 t; cvta.to.shared.u64 t, %1; cvt.u32.u64 %0, t; }" : "=r"(a) : "l"(p));
    return a;
}
__device__ __forceinline__ void ldsm_x4(uint32_t* r, uint32_t addr) {
    asm volatile("ldmatrix.sync.aligned.m8n8.x4.shared.b16 {%0,%1,%2,%3}, [%4];"
        : "=r"(r[0]), "=r"(r[1]), "=r"(r[2]), "=r"(r[3]) : "r"(addr));
}
__device__ __forceinline__ void mma_f16(float* c, const uint32_t* a, const uint32_t* b) {
    asm volatile("mma.sync.aligned.m16n8k16.row.col.f32.f16.f16.f32 "
        "{%0,%1,%2,%3}, {%4,%5,%6,%7}, {%8,%9}, {%0,%1,%2,%3};"
        : "+f"(c[0]), "+f"(c[1]), "+f"(c[2]), "+f"(c[3])
        : "r"(a[0]), "r"(a[1]), "r"(a[2]), "r"(a[3]), "r"(b[0]), "r"(b[1]));
}
__device__ __forceinline__ uint4 cvt8h(const float* a) {
    uint32_t u[4];
#pragma unroll
    for (int i = 0; i < 4; i++) {
        __half h0 = __float2half_rn(a[2 * i]);
        __half h1 = __float2half_rn(a[2 * i + 1]);
        u[i] = (uint32_t)__half_as_ushort(h0) | ((uint32_t)__half_as_ushort(h1) << 16);
    }
    return make_uint4(u[0], u[1], u[2], u[3]);
}
__device__ __forceinline__ float fsig(float v)  { return 1.f / (1.f + __expf(-v)); }
__device__ __forceinline__ float ftanh(float v) { return 1.f - 2.f / (__expf(2.f * v) + 1.f); }

template <int NK>
__device__ __forceinline__ void do_gemm(float acc[2][8][4], uint32_t aB, uint32_t bB) {
#pragma unroll
    for (int kt = 0; kt < NK; kt++) {
        uint32_t Af[4]; ldsm_x4(Af, aB + kt * 32);
#pragma unroll
        for (int ch = 0; ch < 2; ch++)
#pragma unroll
            for (int p = 0; p < 4; p++) {
                uint32_t bf[4];
                ldsm_x4(bf, bB + (uint32_t)(ch * 64 * EKP * 2) + kt * 32 + (uint32_t)(p * 16 * EKP * 2));
                mma_f16(acc[ch][2 * p],     Af, bf);
                mma_f16(acc[ch][2 * p + 1], Af, bf + 2);
            }
    }
}

// 40-block spin barrier (blocks 0..NCORR-1 only; all co-resident in wave 1)
__device__ __forceinline__ void gbar(int tgt) {
    __syncthreads();
    if (threadIdx.x == 0) {
        __threadfence();
        atomicAdd(&g_bar, 1);
        while (atomicAdd(&g_bar, 0) < tgt) { __nanosleep(64); }
        __threadfence();
    }
    __syncthreads();
}

// ---------------- edge dtype probe ----------------
__global__ void detect_dtype_kernel(const void* __restrict__ ei) {
    int e = blockIdx.x * blockDim.x + threadIdx.x;
    if (e >= 2 * NEDGE) return;
    long long v = ((const long long*)ei)[e];
    if (v < 0 || v >= NNODE) atomicOr(&g_bad64, 1);
}
__global__ void set_is64_kernel() { g_is64 = g_bad64 ? 0 : 1; }

__device__ __forceinline__ int edge_at(const void* __restrict__ ei, int idx) {
    int s;
    if (g_is64) s = (int)((const long long*)ei)[idx];
    else        s = ((const int*)ei)[idx];
    if (s < 0) s = 0;
    if (s >= NNODE) s = NNODE - 1;
    return s;
}

// ---------------- setup kernels ----------------
__global__ void zero_h_kernel() {
    int i = blockIdx.x * blockDim.x + threadIdx.x;
    if (i < NTOT * HD) g_h[i] = 0.f;
}
__global__ void zero_counts_kernel() {
    int i = blockIdx.x * blockDim.x + threadIdx.x;
    if (i < NNODE) g_degsrc[i] = 0;
    else if (i < 2 * NNODE) g_cnt[i - NNODE] = 0;
    if (i == 0) { g_bad64 = 0; g_bar = 0; }
}
__global__ void count_edges_kernel(const void* __restrict__ ei) {
    int e = blockIdx.x * blockDim.x + threadIdx.x;
    if (e >= NEDGE) return;
    atomicAdd(&g_degsrc[edge_at(ei, e)], 1);
    atomicAdd(&g_cnt[edge_at(ei, NEDGE + e)], 1);
}
__global__ void norm_kernel(const void* __restrict__ ei) {
    int e = blockIdx.x * blockDim.x + threadIdx.x;
    if (e >= NEDGE) return;
    int s = edge_at(ei, e), d = edge_at(ei, NEDGE + e);
    int ds = g_degsrc[s], dd = g_degsrc[d];
    float is = (ds > 0) ? rsqrtf((float)ds) : 0.f;
    float id = (dd > 0) ? rsqrtf((float)dd) : 0.f;
    g_norm[e] = -is * id;
}
__global__ void scan_kernel() {
    __shared__ int sh[1024];
    int t = threadIdx.x;
    int start = t * 5, end = start + 5;
    if (end > NNODE) end = NNODE;
    int s = 0;
    for (int i = start; i < end && i < NNODE; i++) s += g_cnt[i];
    sh[t] = s;
    __syncthreads();
    for (int off = 1; off < 1024; off <<= 1) {
        int v = (t >= off) ? sh[t - off] : 0;
        __syncthreads();
        sh[t] += v;
        __syncthreads();
    }
    int run = (t == 0) ? 0 : sh[t - 1];
    for (int i = start; i < end && i < NNODE; i++) {
        g_off[i] = run; g_cur[i] = run; run += g_cnt[i];
    }
    if (t == 1023) g_off[NNODE] = sh[1023];
}
__global__ void fill_kernel(const void* __restrict__ ei) {
    int e = blockIdx.x * blockDim.x + threadIdx.x;
    if (e >= NEDGE) return;
    int s = edge_at(ei, e), d = edge_at(ei, NEDGE + e);
    int p = atomicAdd(&g_cur[d], 1);
    if (p >= NEDGE) p = NEDGE - 1;
    g_csrsrc[p] = s;
    g_csrw[p]   = g_norm[e];
}

__device__ __forceinline__ float ic_row_elem(const float* W1, const float* b1, int r, int k) {
    switch (r) {
        case 0: return W1[k]        - W1[512 + k];
        case 1: return W1[128 + k]  - W1[640 + k];
        case 2: return W1[256 + k];
        case 3: return W1[384 + k];
        case 4: return 2.f * W1[512 + k];
        case 5: return 2.f * W1[640 + k];
        default: return b1[k];
    }
}
__global__ void build_zr_fold_kernel(const float* __restrict__ W1, const float* __restrict__ b1,
                                     const float* __restrict__ Wz, const float* __restrict__ bz,
                                     const float* __restrict__ Wr, const float* __restrict__ br) {
    int idx = blockIdx.x * blockDim.x + threadIdx.x;
    if (idx >= 7 * 256) return;
    int r = idx / 256, j = idx % 256;
    const float* Wtop = (j < HD) ? Wz : Wr;
    int jj = j & (HD - 1);
    float s = 0.f;
    for (int k = 0; k < HD; k++) s += ic_row_elem(W1, b1, r, k) * Wtop[k * HD + jj];
    if (r < 6) g_M6zr[r * 256 + j] = s;
    else       g_biaszr[j] = s + ((j < HD) ? bz[jj] : br[jj]);
}
__global__ void build_c_fold_kernel(const float* __restrict__ W1, const float* __restrict__ b1,
                                    const float* __restrict__ Wc, const float* __restrict__ bc) {
    int idx = blockIdx.x * blockDim.x + threadIdx.x;
    if (idx >= 7 * HD) return;
    int r = idx / HD, j = idx % HD;
    float s = 0.f;
    for (int k = 0; k < HD; k++) s += ic_row_elem(W1, b1, r, k) * Wc[k * HD + j];
    if (r < 6) g_M6c[r * HD + j] = s;
    else       g_biasc[j] = s + bc[j];
}

// extended B tiles; MUST run after fold kernels
__global__ void build_bext_kernel(const float* __restrict__ W2, const float* __restrict__ Wz,
                                  const float* __restrict__ Wr, const float* __restrict__ Wc,
                                  const float* __restrict__ b2) {
    int idx = blockIdx.x * blockDim.x + threadIdx.x;
    if (idx >= 6 * 128 * 144) return;
    int a = idx / 18432, rem = idx % 18432;
    int n = rem / 144, k = rem % 144;
    float v = 0.f;
    if (a == 0) {
        if (k < 128)       v = W2[k * 128 + n] - W2[32768 + k * 128 + n];
        else if (k == 134) v = b2[n];
    } else if (a == 1) {
        if (k < 128) v = W2[16384 + k * 128 + n];
    } else if (a == 2) {
        if (k < 128) v = 2.f * W2[32768 + k * 128 + n];
    } else if (a == 3) {
        if (k < 128)       v = Wz[(128 + k) * 128 + n];
        else if (k < 134)  v = g_M6zr[(k - 128) * 256 + n];
        else if (k == 134) v = g_biaszr[n];
    } else if (a == 4) {
        if (k < 128)       v = Wr[(128 + k) * 128 + n];
        else if (k < 134)  v = g_M6zr[(k - 128) * 256 + 128 + n];
        else if (k == 134) v = g_biaszr[128 + n];
    } else {
        if (k < 128)       v = Wc[(128 + k) * 128 + n];
        else if (k < 134)  v = g_M6c[(k - 128) * 128 + n];
        else if (k == 134) v = g_biasc[n];
    }
    g_Bext[a][n * 144 + k] = __float2half_rn(v);
}

// ---------------- graph prop (inside corr blocks) ----------------
__device__ void prop_hop(const float* __restrict__ t128in, float* __restrict__ t128out,
                         const float* __restrict__ x2in, float* __restrict__ x2out, int nb) {
    int base = nb * 125;
    int col  = threadIdx.x & 127;
    int half = threadIdx.x >> 7;
    for (int i = half; i < 125; i += 2) {
        int d = base + i;
        int p0 = g_off[d], p1 = g_off[d + 1];
        float acc = 0.f;
        for (int p = p0; p < p1; p++)
            acc = fmaf(g_csrw[p], t128in[(size_t)g_csrsrc[p] * 128 + col], acc);
        t128out[(size_t)d * 128 + col] = acc;
    }
    if (threadIdx.x < 250) {
        int d = base + (threadIdx.x >> 1);
        int c = threadIdx.x & 1;
        int p0 = g_off[d], p1 = g_off[d + 1];
        float acc = 0.f;
        for (int p = p0; p < p1; p++)
            acc = fmaf(g_csrw[p], x2in[g_csrsrc[p] * 2 + c], acc);
        x2out[d * 2 + c] = acc;
    }
}

// ---------------- per-step fused kernel: prop (40 blocks) overlapped with cell ----------------
// smem: A_s [128][EKP] half | B_s [128][EKP] half = 77824 B, 2 CTA/SM
__global__ __launch_bounds__(256, 2)
void step_kernel(const float* __restrict__ x, int t, int bar_base) {
    extern __shared__ __align__(16) char sm[];
    __half* A_s = (__half*)sm;
    __half* B_s = (__half*)(sm + 38912);

    int tid = threadIdx.x, lane = tid & 31, w = tid >> 5;
    int bid = blockIdx.x;
    bool corr = (bid < NCORR);
    int row0 = bid * 128;
    int g = lane >> 2, q = (lane & 3) << 1;
    int lr0 = w * 16 + g, lr1 = lr0 + 8;
    int srr = tid >> 1, skb = (tid & 1) << 6;

    // ---- corr blocks: both prop hops first (others go straight to GEMMs)
    if (corr) {
        prop_hop(g_h, g_P1, x + (size_t)t * NNODE * 2, g_X1, bid);
        gbar(bar_base + NCORR);
        prop_hop(g_P1, g_P2, g_X1, g_X2, bid);
        gbar(bar_base + 2 * NCORR);
    }

    auto stageA = [&](const float* base, int limit) {
        int gr = row0 + srr;
#pragma unroll
        for (int kk = 0; kk < 64; kk += 8) {
            int k0 = skb + kk;
            float a[8];
            if (gr < limit) {
                const float* src = base + (size_t)gr * 128 + k0;
                float4 v0 = *(const float4*)(src);
                float4 v1 = *(const float4*)(src + 4);
                a[0]=v0.x; a[1]=v0.y; a[2]=v0.z; a[3]=v0.w; a[4]=v1.x; a[5]=v1.y; a[6]=v1.z; a[7]=v1.w;
            } else {
#pragma unroll
                for (int i = 0; i < 8; i++) a[i] = 0.f;
            }
            *(uint4*)&A_s[srr * EKP + k0] = cvt8h(a);
        }
    };
    auto stageB = [&](int sel) {
        const __half* Bw = g_Bext[sel];
        for (int i = tid; i < 128 * 18; i += 256) {
            int n = i / 18, k8 = (i % 18) << 3;
            *(uint4*)&B_s[n * EKP + k8] = *(const uint4*)&Bw[n * 144 + k8];
        }
    };

    uint32_t aB = smem_u32(A_s) + ((uint32_t)((lr0 - g + (lane & 15)) * EKP + ((lane >> 4) << 3)) << 1);
    uint32_t bB = smem_u32(B_s) + ((uint32_t)(((lane & 7) + ((lane & 16) >> 1)) * EKP) << 1) + ((lane & 8) << 1);

    // ---- stage h + f-columns; stage B0
    stageA(g_h, NTOT);
    if (tid & 1) {
        int row = row0 + srr;
        int b = row / NNODE, n = row - b * NNODE;
        const float* xr = x + ((size_t)(b * TSTEPS + t) * NNODE + n) * 2;
        float fa[8] = {xr[0], xr[1], 0.f, 0.f, 0.f, 0.f, 1.f, 0.f};
        if (row < NNODE) {
            fa[2] = g_X1[row * 2]; fa[3] = g_X1[row * 2 + 1];
            fa[4] = g_X2[row * 2]; fa[5] = g_X2[row * 2 + 1];
        }
        *(uint4*)&A_s[srr * EKP + 128] = cvt8h(fa);
        float fz[8] = {0.f, 0.f, 0.f, 0.f, 0.f, 0.f, 0.f, 0.f};
        *(uint4*)&A_s[srr * EKP + 136] = cvt8h(fz);
    }
    stageB(0);
    __syncthreads();

    // ---- GEMM1: hc = [h|f,1] @ Bext0^T
    float hca[2][8][4];
#pragma unroll
    for (int c = 0; c < 2; c++)
#pragma unroll
        for (int i = 0; i < 8; i++)
#pragma unroll
            for (int j = 0; j < 4; j++) hca[c][i][j] = 0.f;
    do_gemm<9>(hca, aB, bB);

    if (corr) {
        __syncthreads();
        stageA(g_P1, NNODE);
        stageB(1);
        __syncthreads();
        do_gemm<8>(hca, aB, bB);
        __syncthreads();
        stageA(g_P2, NNODE);
        stageB(2);
        __syncthreads();
        do_gemm<8>(hca, aB, bB);
    }

    // ---- write hc -> A_s cols 0..127 (f columns persist); stage Bz
    __syncthreads();
#pragma unroll
    for (int ch = 0; ch < 2; ch++)
#pragma unroll
        for (int nt = 0; nt < 8; nt++) {
            int c = ch * 64 + nt * 8 + q;
            *(__half2*)&A_s[lr0 * EKP + c] = __floats2half2_rn(hca[ch][nt][0], hca[ch][nt][1]);
            *(__half2*)&A_s[lr1 * EKP + c] = __floats2half2_rn(hca[ch][nt][2], hca[ch][nt][3]);
        }
    stageB(3);
    __syncthreads();

    // ---- GEMM-z: z packed fp16 in regs
    uint32_t zp[2][8][2];
    {
        float acc[2][8][4];
#pragma unroll
        for (int c = 0; c < 2; c++)
#pragma unroll
            for (int i = 0; i < 8; i++)
#pragma unroll
                for (int j = 0; j < 4; j++) acc[c][i][j] = 0.f;
        do_gemm<9>(acc, aB, bB);
#pragma unroll
        for (int ch = 0; ch < 2; ch++)
#pragma unroll
            for (int nt = 0; nt < 8; nt++)
#pragma unroll
                for (int hh = 0; hh < 2; hh++) {
                    __half2 zh = __floats2half2_rn(fsig(acc[ch][nt][hh * 2]), fsig(acc[ch][nt][hh * 2 + 1]));
                    zp[ch][nt][hh] = *(uint32_t*)&zh;
                }
    }
    __syncthreads();
    stageB(4);
    __syncthreads();

    // ---- GEMM-r: sigmoid, multiply into A_s (hc) in place
    {
        float acc[2][8][4];
#pragma unroll
        for (int c = 0; c < 2; c++)
#pragma unroll
            for (int i = 0; i < 8; i++)
#pragma unroll
                for (int j = 0; j < 4; j++) acc[c][i][j] = 0.f;
        do_gemm<9>(acc, aB, bB);
#pragma unroll
        for (int ch = 0; ch < 2; ch++)
#pragma unroll
            for (int nt = 0; nt < 8; nt++)
#pragma unroll
                for (int j = 0; j < 4; j++)
                    acc[ch][nt][j] = fsig(acc[ch][nt][j]);
        __syncthreads();   // all warps done reading A_s via ldsm
#pragma unroll
        for (int ch = 0; ch < 2; ch++)
#pragma unroll
            for (int nt = 0; nt < 8; nt++) {
                int c = ch * 64 + nt * 8 + q;
#pragma unroll
                for (int hh = 0; hh < 2; hh++) {
                    int lrow = hh ? lr1 : lr0;
                    __half2* hp = (__half2*)&A_s[lrow * EKP + c];
                    __half2 rv = __floats2half2_rn(acc[ch][nt][hh * 2], acc[ch][nt][hh * 2 + 1]);
                    *hp = __hmul2(*hp, rv);
                }
            }
    }
    stageB(5);
    __syncthreads();

    // ---- GEMM3: candidate + GRU update -> g_h
    {
        float acc[2][8][4];
#pragma unroll
        for (int c = 0; c < 2; c++)
#pragma unroll
            for (int i = 0; i < 8; i++)
#pragma unroll
                for (int j = 0; j < 4; j++) acc[c][i][j] = 0.f;
        do_gemm<9>(acc, aB, bB);
#pragma unroll
        for (int ch = 0; ch < 2; ch++)
#pragma unroll
            for (int nt = 0; nt < 8; nt++) {
                int c = ch * 64 + nt * 8 + q;
#pragma unroll
                for (int hh = 0; hh < 2; hh++) {
                    int grow = row0 + (hh ? lr1 : lr0);
                    float t0 = ftanh(acc[ch][nt][hh * 2]);
                    float t1 = ftanh(acc[ch][nt][hh * 2 + 1]);
                    float2 zv = __half22float2(*(__half2*)&zp[ch][nt][hh]);
                    float2 hp = *(float2*)&g_h[(size_t)grow * 128 + c];
                    float2 o;
                    o.x = zv.x * hp.x + (1.f - zv.x) * t0;
                    o.y = zv.y * hp.y + (1.f - zv.y) * t1;
                    *(float2*)&g_h[(size_t)grow * 128 + c] = o;
                }
            }
    }
}

// ---------------- output head ----------------
__global__ void out_kernel(const float* __restrict__ Wo, const float* __restrict__ bo,
                           float* __restrict__ out) {
    int idx = blockIdx.x * blockDim.x + threadIdx.x;
    if (idx >= NTOT * HORZ) return;
    int i = idx / HORZ, hor = idx - i * HORZ;
    const float* hr = g_h + (size_t)i * HD;
    float s = bo[hor];
#pragma unroll 8
    for (int k = 0; k < HD; k++) s = fmaf(hr[k], Wo[k * HORZ + hor], s);
    int b = i / NNODE, n = i - b * NNODE;
    out[(size_t)(b * HORZ + hor) * NNODE + n] = s;
}

// ---------------- launch ----------------
extern "C" void kernel_launch(void* const* d_in, const int* in_sizes, int n_in,
                              void* d_out, int out_size) {
    const float* x  = (const float*)d_in[0];
    const void*  ei = d_in[1];
    const float* W1 = (const float*)d_in[2];
    const float* b1 = (const float*)d_in[3];
    const float* W2 = (const float*)d_in[4];
    const float* b2 = (const float*)d_in[5];
    const float* Wz = (const float*)d_in[6];
    const float* bz = (const float*)d_in[7];
    const float* Wr = (const float*)d_in[8];
    const float* br = (const float*)d_in[9];
    const float* Wc = (const float*)d_in[10];
    const float* bc = (const float*)d_in[11];
    const float* Wo = (const float*)d_in[12];
    const float* bo = (const float*)d_in[13];
    float* out = (float*)d_out;
    (void)in_sizes; (void)n_in; (void)out_size;

    const int SMEM = 2 * 128 * EKP * 2;   // 77824
    cudaFuncSetAttribute(step_kernel, cudaFuncAttributeMaxDynamicSharedMemorySize, SMEM);

    zero_h_kernel<<<(NTOT * HD + 1023) / 1024, 1024>>>();
    zero_counts_kernel<<<(2 * NNODE + 255) / 256, 256>>>();
    detect_dtype_kernel<<<(2 * NEDGE + 255) / 256, 256>>>(ei);
    set_is64_kernel<<<1, 1>>>();
    count_edges_kernel<<<(NEDGE + 255) / 256, 256>>>(ei);
    norm_kernel<<<(NEDGE + 255) / 256, 256>>>(ei);
    scan_kernel<<<1, 1024>>>();
    fill_kernel<<<(NEDGE + 255) / 256, 256>>>(ei);
    build_zr_fold_kernel<<<(7 * 256 + 255) / 256, 256>>>(W1, b1, Wz, bz, Wr, br);
    build_c_fold_kernel<<<(7 * HD + 255) / 256, 256>>>(W1, b1, Wc, bc);
    build_bext_kernel<<<(6 * 128 * 144 + 255) / 256, 256>>>(W2, Wz, Wr, Wc, b2);

    for (int t = 0; t < TSTEPS; t++)
        step_kernel<<<NTOT / 128, 256, SMEM>>>(x, t, t * 2 * NCORR);

    out_kernel<<<(NTOT * HORZ + 255) / 256, 256>>>(Wo, bo, out);
}

// round 15
// speedup vs baseline: 1.0081x; 1.0081x over previous
#include <cuda_runtime.h>
#include <cuda_fp16.h>
#include <math.h>
#include <cstdint>

#define NTOT   160000
#define NNODE  5000
#define NEDGE  80000
#define TSTEPS 12
#define HD     128
#define HORZ   12
#define INF    2

#define EKP 152   // half stride for extended K=144 tiles
#define NCORR 40  // 40 prop blocks / 40 corr cell blocks

// ---------------- static device scratch ----------------
__device__ float g_h   [NTOT * HD];
__device__ float g_P1  [NNODE * HD];
__device__ float g_P2  [NNODE * HD];
__device__ float g_X1  [NNODE * INF];
__device__ float g_X2  [NNODE * INF];
__device__ float g_norm[NEDGE];
__device__ int   g_degsrc[NNODE];
__device__ int   g_cnt [NNODE];
__device__ int   g_off [NNODE + 1];
__device__ int   g_cur [NNODE];
__device__ int   g_csrsrc[NEDGE];
__device__ float g_csrw  [NEDGE];
__device__ float g_M6zr  [6 * 2 * HD];
__device__ float g_biaszr[2 * HD];
__device__ float g_M6c   [6 * HD];
__device__ float g_biasc [HD];
__device__ int   g_bad64;
__device__ int   g_is64;
__device__ int   g_bar;    // prop barrier counter (reset each replay; +80 per step)

// extended fp16 B tiles [n][144]: 0:A2eff(+b2) 1:W2[1] 2:2*W2[2] 3:Wz+M6z+bias 4:Wr+M6r+bias 5:Wc+M6c+bias
__device__ __align__(16) __half g_Bext[6][128 * 144];

// ---------------- warp-MMA primitives ----------------
__device__ __forceinline__ uint32_t smem_u32(const void* p) {
    uint32_t a;
    asm("{ .reg .u64 t; cvta.to.shared.u64 t, %1; cvt.u32.u64 %0, t; }" : "=r"(a) : "l"(p));
    return a;
}
__device__ __forceinline__ void ldsm_x4(uint32_t* r, uint32_t addr) {
    asm volatile("ldmatrix.sync.aligned.m8n8.x4.shared.b16 {%0,%1,%2,%3}, [%4];"
        : "=r"(r[0]), "=r"(r[1]), "=r"(r[2]), "=r"(r[3]) : "r"(addr));
}
__device__ __forceinline__ void mma_f16(float* c, const uint32_t* a, const uint32_t* b) {
    asm volatile("mma.sync.aligned.m16n8k16.row.col.f32.f16.f16.f32 "
        "{%0,%1,%2,%3}, {%4,%5,%6,%7}, {%8,%9}, {%0,%1,%2,%3};"
        : "+f"(c[0]), "+f"(c[1]), "+f"(c[2]), "+f"(c[3])
        : "r"(a[0]), "r"(a[1]), "r"(a[2]), "r"(a[3]), "r"(b[0]), "r"(b[1]));
}
__device__ __forceinline__ uint4 cvt8h(const float* a) {
    uint32_t u[4];
#pragma unroll
    for (int i = 0; i < 4; i++) {
        __half h0 = __float2half_rn(a[2 * i]);
        __half h1 = __float2half_rn(a[2 * i + 1]);
        u[i] = (uint32_t)__half_as_ushort(h0) | ((uint32_t)__half_as_ushort(h1) << 16);
    }
    return make_uint4(u[0], u[1], u[2], u[3]);
}
__device__ __forceinline__ float fsig(float v)  { return 1.f / (1.f + __expf(-v)); }
__device__ __forceinline__ float ftanh(float v) { return 1.f - 2.f / (__expf(2.f * v) + 1.f); }

template <int NK>
__device__ __forceinline__ void do_gemm(float acc[2][8][4], uint32_t aB, uint32_t bB) {
#pragma unroll
    for (int kt = 0; kt < NK; kt++) {
        uint32_t Af[4]; ldsm_x4(Af, aB + kt * 32);
#pragma unroll
        for (int ch = 0; ch < 2; ch++)
#pragma unroll
            for (int p = 0; p < 4; p++) {
                uint32_t bf[4];
                ldsm_x4(bf, bB + (uint32_t)(ch * 64 * EKP * 2) + kt * 32 + (uint32_t)(p * 16 * EKP * 2));
                mma_f16(acc[ch][2 * p],     Af, bf);
                mma_f16(acc[ch][2 * p + 1], Af, bf + 2);
            }
    }
}

// ---------------- edge dtype probe ----------------
__global__ void detect_dtype_kernel(const void* __restrict__ ei) {
    int e = blockIdx.x * blockDim.x + threadIdx.x;
    if (e >= 2 * NEDGE) return;
    long long v = ((const long long*)ei)[e];
    if (v < 0 || v >= NNODE) atomicOr(&g_bad64, 1);
}
__global__ void set_is64_kernel() { g_is64 = g_bad64 ? 0 : 1; }

__device__ __forceinline__ int edge_at(const void* __restrict__ ei, int idx) {
    int s;
    if (g_is64) s = (int)((const long long*)ei)[idx];
    else        s = ((const int*)ei)[idx];
    if (s < 0) s = 0;
    if (s >= NNODE) s = NNODE - 1;
    return s;
}

// ---------------- setup kernels ----------------
__global__ void zero_h_kernel() {
    int i = blockIdx.x * blockDim.x + threadIdx.x;
    if (i < NTOT * HD) g_h[i] = 0.f;
}
__global__ void zero_counts_kernel() {
    int i = blockIdx.x * blockDim.x + threadIdx.x;
    if (i < NNODE) g_degsrc[i] = 0;
    else if (i < 2 * NNODE) g_cnt[i - NNODE] = 0;
    if (i == 0) { g_bad64 = 0; g_bar = 0; }
}
__global__ void count_edges_kernel(const void* __restrict__ ei) {
    int e = blockIdx.x * blockDim.x + threadIdx.x;
    if (e >= NEDGE) return;
    atomicAdd(&g_degsrc[edge_at(ei, e)], 1);
    atomicAdd(&g_cnt[edge_at(ei, NEDGE + e)], 1);
}
__global__ void norm_kernel(const void* __restrict__ ei) {
    int e = blockIdx.x * blockDim.x + threadIdx.x;
    if (e >= NEDGE) return;
    int s = edge_at(ei, e), d = edge_at(ei, NEDGE + e);
    int ds = g_degsrc[s], dd = g_degsrc[d];
    float is = (ds > 0) ? rsqrtf((float)ds) : 0.f;
    float id = (dd > 0) ? rsqrtf((float)dd) : 0.f;
    g_norm[e] = -is * id;
}
__global__ void scan_kernel() {
    __shared__ int sh[1024];
    int t = threadIdx.x;
    int start = t * 5, end = start + 5;
    if (end > NNODE) end = NNODE;
    int s = 0;
    for (int i = start; i < end && i < NNODE; i++) s += g_cnt[i];
    sh[t] = s;
    __syncthreads();
    for (int off = 1; off < 1024; off <<= 1) {
        int v = (t >= off) ? sh[t - off] : 0;
        __syncthreads();
        sh[t] += v;
        __syncthreads();
    }
    int run = (t == 0) ? 0 : sh[t - 1];
    for (int i = start; i < end && i < NNODE; i++) {
        g_off[i] = run; g_cur[i] = run; run += g_cnt[i];
    }
    if (t == 1023) g_off[NNODE] = sh[1023];
}
__global__ void fill_kernel(const void* __restrict__ ei) {
    int e = blockIdx.x * blockDim.x + threadIdx.x;
    if (e >= NEDGE) return;
    int s = edge_at(ei, e), d = edge_at(ei, NEDGE + e);
    int p = atomicAdd(&g_cur[d], 1);
    if (p >= NEDGE) p = NEDGE - 1;
    g_csrsrc[p] = s;
    g_csrw[p]   = g_norm[e];
}

__device__ __forceinline__ float ic_row_elem(const float* W1, const float* b1, int r, int k) {
    switch (r) {
        case 0: return W1[k]        - W1[512 + k];
        case 1: return W1[128 + k]  - W1[640 + k];
        case 2: return W1[256 + k];
        case 3: return W1[384 + k];
        case 4: return 2.f * W1[512 + k];
        case 5: return 2.f * W1[640 + k];
        default: return b1[k];
    }
}
__global__ void build_zr_fold_kernel(const float* __restrict__ W1, const float* __restrict__ b1,
                                     const float* __restrict__ Wz, const float* __restrict__ bz,
                                     const float* __restrict__ Wr, const float* __restrict__ br) {
    int idx = blockIdx.x * blockDim.x + threadIdx.x;
    if (idx >= 7 * 256) return;
    int r = idx / 256, j = idx % 256;
    const float* Wtop = (j < HD) ? Wz : Wr;
    int jj = j & (HD - 1);
    float s = 0.f;
    for (int k = 0; k < HD; k++) s += ic_row_elem(W1, b1, r, k) * Wtop[k * HD + jj];
    if (r < 6) g_M6zr[r * 256 + j] = s;
    else       g_biaszr[j] = s + ((j < HD) ? bz[jj] : br[jj]);
}
__global__ void build_c_fold_kernel(const float* __restrict__ W1, const float* __restrict__ b1,
                                    const float* __restrict__ Wc, const float* __restrict__ bc) {
    int idx = blockIdx.x * blockDim.x + threadIdx.x;
    if (idx >= 7 * HD) return;
    int r = idx / HD, j = idx % HD;
    float s = 0.f;
    for (int k = 0; k < HD; k++) s += ic_row_elem(W1, b1, r, k) * Wc[k * HD + j];
    if (r < 6) g_M6c[r * HD + j] = s;
    else       g_biasc[j] = s + bc[j];
}

// extended B tiles; MUST run after fold kernels
__global__ void build_bext_kernel(const float* __restrict__ W2, const float* __restrict__ Wz,
                                  const float* __restrict__ Wr, const float* __restrict__ Wc,
                                  const float* __restrict__ b2) {
    int idx = blockIdx.x * blockDim.x + threadIdx.x;
    if (idx >= 6 * 128 * 144) return;
    int a = idx / 18432, rem = idx % 18432;
    int n = rem / 144, k = rem % 144;
    float v = 0.f;
    if (a == 0) {
        if (k < 128)       v = W2[k * 128 + n] - W2[32768 + k * 128 + n];
        else if (k == 134) v = b2[n];
    } else if (a == 1) {
        if (k < 128) v = W2[16384 + k * 128 + n];
    } else if (a == 2) {
        if (k < 128) v = 2.f * W2[32768 + k * 128 + n];
    } else if (a == 3) {
        if (k < 128)       v = Wz[(128 + k) * 128 + n];
        else if (k < 134)  v = g_M6zr[(k - 128) * 256 + n];
        else if (k == 134) v = g_biaszr[n];
    } else if (a == 4) {
        if (k < 128)       v = Wr[(128 + k) * 128 + n];
        else if (k < 134)  v = g_M6zr[(k - 128) * 256 + 128 + n];
        else if (k == 134) v = g_biaszr[128 + n];
    } else {
        if (k < 128)       v = Wc[(128 + k) * 128 + n];
        else if (k < 134)  v = g_M6c[(k - 128) * 128 + n];
        else if (k == 134) v = g_biasc[n];
    }
    g_Bext[a][n * 144 + k] = __float2half_rn(v);
}

// ---------------- graph prop (dedicated blocks) ----------------
__device__ void prop_hop(const float* __restrict__ t128in, float* __restrict__ t128out,
                         const float* __restrict__ x2in, float* __restrict__ x2out, int nb) {
    int base = nb * 125;
    int col  = threadIdx.x & 127;
    int half = threadIdx.x >> 7;
    for (int i = half; i < 125; i += 2) {
        int d = base + i;
        int p0 = g_off[d], p1 = g_off[d + 1];
        float acc = 0.f;
        for (int p = p0; p < p1; p++)
            acc = fmaf(g_csrw[p], t128in[(size_t)g_csrsrc[p] * 128 + col], acc);
        t128out[(size_t)d * 128 + col] = acc;
    }
    if (threadIdx.x < 250) {
        int d = base + (threadIdx.x >> 1);
        int c = threadIdx.x & 1;
        int p0 = g_off[d], p1 = g_off[d + 1];
        float acc = 0.f;
        for (int p = p0; p < p1; p++)
            acc = fmaf(g_csrw[p], x2in[g_csrsrc[p] * 2 + c], acc);
        x2out[d * 2 + c] = acc;
    }
}

// ---------------- per-step mega kernel ----------------
// ids 0..39: prop-only blocks.  ids 40..1289: cell blocks (row0 = (bid-40)*128).
// smem: A_s [128][EKP] half | B_s [128][EKP] half = 77824 B, 2 CTA/SM
__global__ __launch_bounds__(256, 2)
void step_kernel(const float* __restrict__ x, int t, int bar_base) {
    int tid = threadIdx.x;
    int bid = blockIdx.x;

    // ================= prop blocks =================
    if (bid < NCORR) {
        prop_hop(g_h, g_P1, x + (size_t)t * NNODE * 2, g_X1, bid);
        // barrier between hops (prop blocks only)
        __syncthreads();
        if (tid == 0) {
            __threadfence();
            atomicAdd(&g_bar, 1);
            while (atomicAdd(&g_bar, 0) < bar_base + NCORR) { __nanosleep(64); }
            __threadfence();
        }
        __syncthreads();
        prop_hop(g_P1, g_P2, g_X1, g_X2, bid);
        __syncthreads();
        if (tid == 0) {
            __threadfence();
            atomicAdd(&g_bar, 1);   // completion arrive; reaches bar_base + 2*NCORR
        }
        return;
    }

    // ================= cell blocks =================
    extern __shared__ __align__(16) char sm[];
    __half* A_s = (__half*)sm;
    __half* B_s = (__half*)(sm + 38912);

    int lane = tid & 31, w = tid >> 5;
    int cid = bid - NCORR;
    bool corr = (cid < NCORR);
    int row0 = cid * 128;
    int g = lane >> 2, q = (lane & 3) << 1;
    int lr0 = w * 16 + g, lr1 = lr0 + 8;
    int srr = tid >> 1, skb = (tid & 1) << 6;

    // corr cell blocks: wait for prop completion before touching X1/X2/P1/P2
    if (corr) {
        if (tid == 0) {
            while (atomicAdd(&g_bar, 0) < bar_base + 2 * NCORR) { __nanosleep(128); }
            __threadfence();
        }
        __syncthreads();
    }

    auto stageA = [&](const float* base, int limit) {
        int gr = row0 + srr;
#pragma unroll
        for (int kk = 0; kk < 64; kk += 8) {
            int k0 = skb + kk;
            float a[8];
            if (gr < limit) {
                const float* src = base + (size_t)gr * 128 + k0;
                float4 v0 = *(const float4*)(src);
                float4 v1 = *(const float4*)(src + 4);
                a[0]=v0.x; a[1]=v0.y; a[2]=v0.z; a[3]=v0.w; a[4]=v1.x; a[5]=v1.y; a[6]=v1.z; a[7]=v1.w;
            } else {
#pragma unroll
                for (int i = 0; i < 8; i++) a[i] = 0.f;
            }
            *(uint4*)&A_s[srr * EKP + k0] = cvt8h(a);
        }
    };
    auto stageB = [&](int sel) {
        const __half* Bw = g_Bext[sel];
        for (int i = tid; i < 128 * 18; i += 256) {
            int n = i / 18, k8 = (i % 18) << 3;
            *(uint4*)&B_s[n * EKP + k8] = *(const uint4*)&Bw[n * 144 + k8];
        }
    };

    uint32_t aB = smem_u32(A_s) + ((uint32_t)((lr0 - g + (lane & 15)) * EKP + ((lane >> 4) << 3)) << 1);
    uint32_t bB = smem_u32(B_s) + ((uint32_t)(((lane & 7) + ((lane & 16) >> 1)) * EKP) << 1) + ((lane & 8) << 1);

    // ---- stage h + f-columns; stage B0
    stageA(g_h, NTOT);
    if (tid & 1) {
        int row = row0 + srr;
        int b = row / NNODE, n = row - b * NNODE;
        const float* xr = x + ((size_t)(b * TSTEPS + t) * NNODE + n) * 2;
        float fa[8] = {xr[0], xr[1], 0.f, 0.f, 0.f, 0.f, 1.f, 0.f};
        if (row < NNODE) {
            fa[2] = g_X1[row * 2]; fa[3] = g_X1[row * 2 + 1];
            fa[4] = g_X2[row * 2]; fa[5] = g_X2[row * 2 + 1];
        }
        *(uint4*)&A_s[srr * EKP + 128] = cvt8h(fa);
        float fz[8] = {0.f, 0.f, 0.f, 0.f, 0.f, 0.f, 0.f, 0.f};
        *(uint4*)&A_s[srr * EKP + 136] = cvt8h(fz);
    }
    stageB(0);
    __syncthreads();

    // ---- GEMM1: hc = [h|f,1] @ Bext0^T
    float hca[2][8][4];
#pragma unroll
    for (int c = 0; c < 2; c++)
#pragma unroll
        for (int i = 0; i < 8; i++)
#pragma unroll
            for (int j = 0; j < 4; j++) hca[c][i][j] = 0.f;
    do_gemm<9>(hca, aB, bB);

    if (corr) {
        __syncthreads();
        stageA(g_P1, NNODE);
        stageB(1);
        __syncthreads();
        do_gemm<8>(hca, aB, bB);
        __syncthreads();
        stageA(g_P2, NNODE);
        stageB(2);
        __syncthreads();
        do_gemm<8>(hca, aB, bB);
    }

    // ---- write hc -> A_s cols 0..127 (f columns persist); stage Bz
    __syncthreads();
#pragma unroll
    for (int ch = 0; ch < 2; ch++)
#pragma unroll
        for (int nt = 0; nt < 8; nt++) {
            int c = ch * 64 + nt * 8 + q;
            *(__half2*)&A_s[lr0 * EKP + c] = __floats2half2_rn(hca[ch][nt][0], hca[ch][nt][1]);
            *(__half2*)&A_s[lr1 * EKP + c] = __floats2half2_rn(hca[ch][nt][2], hca[ch][nt][3]);
        }
    stageB(3);
    __syncthreads();

    // ---- GEMM-z: z packed fp16 in regs
    uint32_t zp[2][8][2];
    {
        float acc[2][8][4];
#pragma unroll
        for (int c = 0; c < 2; c++)
#pragma unroll
            for (int i = 0; i < 8; i++)
#pragma unroll
                for (int j = 0; j < 4; j++) acc[c][i][j] = 0.f;
        do_gemm<9>(acc, aB, bB);
#pragma unroll
        for (int ch = 0; ch < 2; ch++)
#pragma unroll
            for (int nt = 0; nt < 8; nt++)
#pragma unroll
                for (int hh = 0; hh < 2; hh++) {
                    __half2 zh = __floats2half2_rn(fsig(acc[ch][nt][hh * 2]), fsig(acc[ch][nt][hh * 2 + 1]));
                    zp[ch][nt][hh] = *(uint32_t*)&zh;
                }
    }
    __syncthreads();
    stageB(4);
    __syncthreads();

    // ---- GEMM-r: sigmoid, multiply into A_s (hc) in place
    {
        float acc[2][8][4];
#pragma unroll
        for (int c = 0; c < 2; c++)
#pragma unroll
            for (int i = 0; i < 8; i++)
#pragma unroll
                for (int j = 0; j < 4; j++) acc[c][i][j] = 0.f;
        do_gemm<9>(acc, aB, bB);
#pragma unroll
        for (int ch = 0; ch < 2; ch++)
#pragma unroll
            for (int nt = 0; nt < 8; nt++)
#pragma unroll
                for (int j = 0; j < 4; j++)
                    acc[ch][nt][j] = fsig(acc[ch][nt][j]);
        __syncthreads();   // all warps done reading A_s via ldsm
#pragma unroll
        for (int ch = 0; ch < 2; ch++)
#pragma unroll
            for (int nt = 0; nt < 8; nt++) {
                int c = ch * 64 + nt * 8 + q;
#pragma unroll
                for (int hh = 0; hh < 2; hh++) {
                    int lrow = hh ? lr1 : lr0;
                    __half2* hp = (__half2*)&A_s[lrow * EKP + c];
                    __half2 rv = __floats2half2_rn(acc[ch][nt][hh * 2], acc[ch][nt][hh * 2 + 1]);
                    *hp = __hmul2(*hp, rv);
                }
            }
    }
    stageB(5);
    __syncthreads();

    // ---- GEMM3: candidate + GRU update -> g_h
    {
        float acc[2][8][4];
#pragma unroll
        for (int c = 0; c < 2; c++)
#pragma unroll
            for (int i = 0; i < 8; i++)
#pragma unroll
                for (int j = 0; j < 4; j++) acc[c][i][j] = 0.f;
        do_gemm<9>(acc, aB, bB);
#pragma unroll
        for (int ch = 0; ch < 2; ch++)
#pragma unroll
            for (int nt = 0; nt < 8; nt++) {
                int c = ch * 64 + nt * 8 + q;
#pragma unroll
                for (int hh = 0; hh < 2; hh++) {
                    int grow = row0 + (hh ? lr1 : lr0);
                    float t0 = ftanh(acc[ch][nt][hh * 2]);
                    float t1 = ftanh(acc[ch][nt][hh * 2 + 1]);
                    float2 zv = __half22float2(*(__half2*)&zp[ch][nt][hh]);
                    float2 hp = *(float2*)&g_h[(size_t)grow * 128 + c];
                    float2 o;
                    o.x = zv.x * hp.x + (1.f - zv.x) * t0;
                    o.y = zv.y * hp.y + (1.f - zv.y) * t1;
                    *(float2*)&g_h[(size_t)grow * 128 + c] = o;
                }
            }
    }
}

// ---------------- output head ----------------
__global__ void out_kernel(const float* __restrict__ Wo, const float* __restrict__ bo,
                           float* __restrict__ out) {
    int idx = blockIdx.x * blockDim.x + threadIdx.x;
    if (idx >= NTOT * HORZ) return;
    int i = idx / HORZ, hor = idx - i * HORZ;
    const float* hr = g_h + (size_t)i * HD;
    float s = bo[hor];
#pragma unroll 8
    for (int k = 0; k < HD; k++) s = fmaf(hr[k], Wo[k * HORZ + hor], s);
    int b = i / NNODE, n = i - b * NNODE;
    out[(size_t)(b * HORZ + hor) * NNODE + n] = s;
}

// ---------------- launch ----------------
extern "C" void kernel_launch(void* const* d_in, const int* in_sizes, int n_in,
                              void* d_out, int out_size) {
    const float* x  = (const float*)d_in[0];
    const void*  ei = d_in[1];
    const float* W1 = (const float*)d_in[2];
    const float* b1 = (const float*)d_in[3];
    const float* W2 = (const float*)d_in[4];
    const float* b2 = (const float*)d_in[5];
    const float* Wz = (const float*)d_in[6];
    const float* bz = (const float*)d_in[7];
    const float* Wr = (const float*)d_in[8];
    const float* br = (const float*)d_in[9];
    const float* Wc = (const float*)d_in[10];
    const float* bc = (const float*)d_in[11];
    const float* Wo = (const float*)d_in[12];
    const float* bo = (const float*)d_in[13];
    float* out = (float*)d_out;
    (void)in_sizes; (void)n_in; (void)out_size;

    const int SMEM = 2 * 128 * EKP * 2;   // 77824
    cudaFuncSetAttribute(step_kernel, cudaFuncAttributeMaxDynamicSharedMemorySize, SMEM);

    zero_h_kernel<<<(NTOT * HD + 1023) / 1024, 1024>>>();
    zero_counts_kernel<<<(2 * NNODE + 255) / 256, 256>>>();
    detect_dtype_kernel<<<(2 * NEDGE + 255) / 256, 256>>>(ei);
    set_is64_kernel<<<1, 1>>>();
    count_edges_kernel<<<(NEDGE + 255) / 256, 256>>>(ei);
    norm_kernel<<<(NEDGE + 255) / 256, 256>>>(ei);
    scan_kernel<<<1, 1024>>>();
    fill_kernel<<<(NEDGE + 255) / 256, 256>>>(ei);
    build_zr_fold_kernel<<<(7 * 256 + 255) / 256, 256>>>(W1, b1, Wz, bz, Wr, br);
    build_c_fold_kernel<<<(7 * HD + 255) / 256, 256>>>(W1, b1, Wc, bc);
    build_bext_kernel<<<(6 * 128 * 144 + 255) / 256, 256>>>(W2, Wz, Wr, Wc, b2);

    for (int t = 0; t < TSTEPS; t++)
        step_kernel<<<NTOT / 128 + NCORR, 256, SMEM>>>(x, t, t * 2 * NCORR);

    out_kernel<<<(NTOT * HORZ + 255) / 256, 256>>>(Wo, bo, out);
}

// round 16
// speedup vs baseline: 1.1032x; 1.0944x over previous
#include <cuda_runtime.h>
#include <cuda_fp16.h>
#include <math.h>
#include <cstdint>

#define NTOT   160000
#define NNODE  5000
#define NEDGE  80000
#define TSTEPS 12
#define HD     128
#define HORZ   12
#define INF    2

#define EKP 152   // half stride for extended K=144 tiles

// ---------------- static device scratch ----------------
__device__ float g_h   [NTOT * HD];
__device__ float g_P1  [NNODE * HD];
__device__ float g_P2  [NNODE * HD];
__device__ float g_X1  [NNODE * INF];
__device__ float g_X2  [NNODE * INF];
__device__ float g_norm[NEDGE];
__device__ int   g_degsrc[NNODE];
__device__ int   g_cnt [NNODE];
__device__ int   g_off [NNODE + 1];
__device__ int   g_cur [NNODE];
__device__ int   g_csrsrc[NEDGE];
__device__ float g_csrw  [NEDGE];
__device__ float g_M6zr  [6 * 2 * HD];
__device__ float g_biaszr[2 * HD];
__device__ float g_M6c   [6 * HD];
__device__ float g_biasc [HD];
__device__ int   g_bad64;
__device__ int   g_is64;

// extended fp16 B tiles [n][144]: 0:A2eff(+b2) 1:W2[1] 2:2*W2[2] 3:Wz+M6z+bias 4:Wr+M6r+bias 5:Wc+M6c+bias
__device__ __align__(16) __half g_Bext[6][128 * 144];

// ---------------- warp-MMA primitives ----------------
__device__ __forceinline__ uint32_t smem_u32(const void* p) {
    uint32_t a;
    asm("{ .reg .u64 t; cvta.to.shared.u64 t, %1; cvt.u32.u64 %0, t; }" : "=r"(a) : "l"(p));
    return a;
}
__device__ __forceinline__ void ldsm_x4(uint32_t* r, uint32_t addr) {
    asm volatile("ldmatrix.sync.aligned.m8n8.x4.shared.b16 {%0,%1,%2,%3}, [%4];"
        : "=r"(r[0]), "=r"(r[1]), "=r"(r[2]), "=r"(r[3]) : "r"(addr));
}
__device__ __forceinline__ void mma_f16(float* c, const uint32_t* a, const uint32_t* b) {
    asm volatile("mma.sync.aligned.m16n8k16.row.col.f32.f16.f16.f32 "
        "{%0,%1,%2,%3}, {%4,%5,%6,%7}, {%8,%9}, {%0,%1,%2,%3};"
        : "+f"(c[0]), "+f"(c[1]), "+f"(c[2]), "+f"(c[3])
        : "r"(a[0]), "r"(a[1]), "r"(a[2]), "r"(a[3]), "r"(b[0]), "r"(b[1]));
}
__device__ __forceinline__ uint4 cvt8h(const float* a) {
    uint32_t u[4];
#pragma unroll
    for (int i = 0; i < 4; i++) {
        __half h0 = __float2half_rn(a[2 * i]);
        __half h1 = __float2half_rn(a[2 * i + 1]);
        u[i] = (uint32_t)__half_as_ushort(h0) | ((uint32_t)__half_as_ushort(h1) << 16);
    }
    return make_uint4(u[0], u[1], u[2], u[3]);
}
__device__ __forceinline__ float fsig(float v)  { return 1.f / (1.f + __expf(-v)); }
__device__ __forceinline__ float ftanh(float v) { return 1.f - 2.f / (__expf(2.f * v) + 1.f); }

template <int NK>
__device__ __forceinline__ void do_gemm(float acc[2][8][4], uint32_t aB, uint32_t bB) {
#pragma unroll
    for (int kt = 0; kt < NK; kt++) {
        uint32_t Af[4]; ldsm_x4(Af, aB + kt * 32);
#pragma unroll
        for (int ch = 0; ch < 2; ch++)
#pragma unroll
            for (int p = 0; p < 4; p++) {
                uint32_t bf[4];
                ldsm_x4(bf, bB + (uint32_t)(ch * 64 * EKP * 2) + kt * 32 + (uint32_t)(p * 16 * EKP * 2));
                mma_f16(acc[ch][2 * p],     Af, bf);
                mma_f16(acc[ch][2 * p + 1], Af, bf + 2);
            }
    }
}

// ---------------- edge dtype probe ----------------
__global__ void detect_dtype_kernel(const void* __restrict__ ei) {
    int e = blockIdx.x * blockDim.x + threadIdx.x;
    if (e >= 2 * NEDGE) return;
    long long v = ((const long long*)ei)[e];
    if (v < 0 || v >= NNODE) atomicOr(&g_bad64, 1);
}
__global__ void set_is64_kernel() { g_is64 = g_bad64 ? 0 : 1; }

__device__ __forceinline__ int edge_at(const void* __restrict__ ei, int idx) {
    int s;
    if (g_is64) s = (int)((const long long*)ei)[idx];
    else        s = ((const int*)ei)[idx];
    if (s < 0) s = 0;
    if (s >= NNODE) s = NNODE - 1;
    return s;
}

// ---------------- setup kernels ----------------
__global__ void zero_h_kernel() {
    int i = blockIdx.x * blockDim.x + threadIdx.x;
    if (i < NTOT * HD) g_h[i] = 0.f;
}
__global__ void zero_counts_kernel() {
    int i = blockIdx.x * blockDim.x + threadIdx.x;
    if (i < NNODE) g_degsrc[i] = 0;
    else if (i < 2 * NNODE) g_cnt[i - NNODE] = 0;
    if (i == 0) g_bad64 = 0;
}
__global__ void count_edges_kernel(const void* __restrict__ ei) {
    int e = blockIdx.x * blockDim.x + threadIdx.x;
    if (e >= NEDGE) return;
    atomicAdd(&g_degsrc[edge_at(ei, e)], 1);
    atomicAdd(&g_cnt[edge_at(ei, NEDGE + e)], 1);
}
__global__ void norm_kernel(const void* __restrict__ ei) {
    int e = blockIdx.x * blockDim.x + threadIdx.x;
    if (e >= NEDGE) return;
    int s = edge_at(ei, e), d = edge_at(ei, NEDGE + e);
    int ds = g_degsrc[s], dd = g_degsrc[d];
    float is = (ds > 0) ? rsqrtf((float)ds) : 0.f;
    float id = (dd > 0) ? rsqrtf((float)dd) : 0.f;
    g_norm[e] = -is * id;
}
__global__ void scan_kernel() {
    __shared__ int sh[1024];
    int t = threadIdx.x;
    int start = t * 5, end = start + 5;
    if (end > NNODE) end = NNODE;
    int s = 0;
    for (int i = start; i < end && i < NNODE; i++) s += g_cnt[i];
    sh[t] = s;
    __syncthreads();
    for (int off = 1; off < 1024; off <<= 1) {
        int v = (t >= off) ? sh[t - off] : 0;
        __syncthreads();
        sh[t] += v;
        __syncthreads();
    }
    int run = (t == 0) ? 0 : sh[t - 1];
    for (int i = start; i < end && i < NNODE; i++) {
        g_off[i] = run; g_cur[i] = run; run += g_cnt[i];
    }
    if (t == 1023) g_off[NNODE] = sh[1023];
}
__global__ void fill_kernel(const void* __restrict__ ei) {
    int e = blockIdx.x * blockDim.x + threadIdx.x;
    if (e >= NEDGE) return;
    int s = edge_at(ei, e), d = edge_at(ei, NEDGE + e);
    int p = atomicAdd(&g_cur[d], 1);
    if (p >= NEDGE) p = NEDGE - 1;
    g_csrsrc[p] = s;
    g_csrw[p]   = g_norm[e];
}

__device__ __forceinline__ float ic_row_elem(const float* W1, const float* b1, int r, int k) {
    switch (r) {
        case 0: return W1[k]        - W1[512 + k];
        case 1: return W1[128 + k]  - W1[640 + k];
        case 2: return W1[256 + k];
        case 3: return W1[384 + k];
        case 4: return 2.f * W1[512 + k];
        case 5: return 2.f * W1[640 + k];
        default: return b1[k];
    }
}
__global__ void build_zr_fold_kernel(const float* __restrict__ W1, const float* __restrict__ b1,
                                     const float* __restrict__ Wz, const float* __restrict__ bz,
                                     const float* __restrict__ Wr, const float* __restrict__ br) {
    int idx = blockIdx.x * blockDim.x + threadIdx.x;
    if (idx >= 7 * 256) return;
    int r = idx / 256, j = idx % 256;
    const float* Wtop = (j < HD) ? Wz : Wr;
    int jj = j & (HD - 1);
    float s = 0.f;
    for (int k = 0; k < HD; k++) s += ic_row_elem(W1, b1, r, k) * Wtop[k * HD + jj];
    if (r < 6) g_M6zr[r * 256 + j] = s;
    else       g_biaszr[j] = s + ((j < HD) ? bz[jj] : br[jj]);
}
__global__ void build_c_fold_kernel(const float* __restrict__ W1, const float* __restrict__ b1,
                                    const float* __restrict__ Wc, const float* __restrict__ bc) {
    int idx = blockIdx.x * blockDim.x + threadIdx.x;
    if (idx >= 7 * HD) return;
    int r = idx / HD, j = idx % HD;
    float s = 0.f;
    for (int k = 0; k < HD; k++) s += ic_row_elem(W1, b1, r, k) * Wc[k * HD + j];
    if (r < 6) g_M6c[r * HD + j] = s;
    else       g_biasc[j] = s + bc[j];
}

// extended B tiles; MUST run after fold kernels
__global__ void build_bext_kernel(const float* __restrict__ W2, const float* __restrict__ Wz,
                                  const float* __restrict__ Wr, const float* __restrict__ Wc,
                                  const float* __restrict__ b2) {
    int idx = blockIdx.x * blockDim.x + threadIdx.x;
    if (idx >= 6 * 128 * 144) return;
    int a = idx / 18432, rem = idx % 18432;
    int n = rem / 144, k = rem % 144;
    float v = 0.f;
    if (a == 0) {
        if (k < 128)       v = W2[k * 128 + n] - W2[32768 + k * 128 + n];
        else if (k == 134) v = b2[n];
    } else if (a == 1) {
        if (k < 128) v = W2[16384 + k * 128 + n];
    } else if (a == 2) {
        if (k < 128) v = 2.f * W2[32768 + k * 128 + n];
    } else if (a == 3) {
        if (k < 128)       v = Wz[(128 + k) * 128 + n];
        else if (k < 134)  v = g_M6zr[(k - 128) * 256 + n];
        else if (k == 134) v = g_biaszr[n];
    } else if (a == 4) {
        if (k < 128)       v = Wr[(128 + k) * 128 + n];
        else if (k < 134)  v = g_M6zr[(k - 128) * 256 + 128 + n];
        else if (k == 134) v = g_biaszr[128 + n];
    } else {
        if (k < 128)       v = Wc[(128 + k) * 128 + n];
        else if (k < 134)  v = g_M6c[(k - 128) * 128 + n];
        else if (k == 134) v = g_biasc[n];
    }
    g_Bext[a][n * 144 + k] = __float2half_rn(v);
}

// ---------------- graph propagation (merged 128-wide + 2-wide) ----------------
__global__ void prop_kernel(int sel, const float* __restrict__ xin) {
    const float* tin  = sel ? g_P1 : g_h;
    float*       tout = sel ? g_P2 : g_P1;
    const float* x2i  = sel ? g_X1 : xin;
    float*       x2o  = sel ? g_X2 : g_X1;
    int d = blockIdx.x, j = threadIdx.x;
    int p0 = g_off[d], p1 = g_off[d + 1];
    float acc = 0.f;
    for (int p = p0; p < p1; p++)
        acc = fmaf(g_csrw[p], tin[(size_t)g_csrsrc[p] * HD + j], acc);
    tout[(size_t)d * HD + j] = acc;
    if (j < 2) {
        float a2 = 0.f;
        for (int p = p0; p < p1; p++)
            a2 = fmaf(g_csrw[p], x2i[g_csrsrc[p] * 2 + j], a2);
        x2o[d * 2 + j] = a2;
    }
}

// ---------------- fused TGCN cell (2 CTA/SM, rank6+bias folded into GEMM) ----------------
// smem: A_s [128][EKP] half (38912 B) | B_s [128][EKP] half (38912 B) = 77824 B
__global__ __launch_bounds__(256, 2)
void cell_kernel(const float* __restrict__ x, int t) {
    extern __shared__ __align__(16) char sm[];
    __half* A_s = (__half*)sm;
    __half* B_s = (__half*)(sm + 38912);

    int tid = threadIdx.x, lane = tid & 31, w = tid >> 5;
    int row0 = blockIdx.x * 128;
    bool corr = (row0 < NNODE);
    int g = lane >> 2, q = (lane & 3) << 1;
    int lr0 = w * 16 + g, lr1 = lr0 + 8;

    int srr = tid >> 1, skb = (tid & 1) << 6;

    // plain-path A staging (rows always valid: NTOT % 128 == 0)
    auto stageA = [&](const float* base) {
        const float* src0 = base + (size_t)(row0 + srr) * 128 + skb;
#pragma unroll
        for (int kk = 0; kk < 64; kk += 8) {
            float a[8];
            float4 v0 = *(const float4*)(src0 + kk);
            float4 v1 = *(const float4*)(src0 + kk + 4);
            a[0]=v0.x; a[1]=v0.y; a[2]=v0.z; a[3]=v0.w; a[4]=v1.x; a[5]=v1.y; a[6]=v1.z; a[7]=v1.w;
            *(uint4*)&A_s[srr * EKP + skb + kk] = cvt8h(a);
        }
    };
    // guarded variant for P1/P2 (rows >= NNODE -> 0)
    auto stageAg = [&](const float* base) {
        int gr = row0 + srr;
#pragma unroll
        for (int kk = 0; kk < 64; kk += 8) {
            int k0 = skb + kk;
            float a[8];
            if (gr < NNODE) {
                const float* src = base + (size_t)gr * 128 + k0;
                float4 v0 = *(const float4*)(src);
                float4 v1 = *(const float4*)(src + 4);
                a[0]=v0.x; a[1]=v0.y; a[2]=v0.z; a[3]=v0.w; a[4]=v1.x; a[5]=v1.y; a[6]=v1.z; a[7]=v1.w;
            } else {
#pragma unroll
                for (int i = 0; i < 8; i++) a[i] = 0.f;
            }
            *(uint4*)&A_s[srr * EKP + k0] = cvt8h(a);
        }
    };
    auto stageB = [&](int sel) {
        const __half* Bw = g_Bext[sel];
        for (int i = tid; i < 128 * 18; i += 256) {
            int n = i / 18, k8 = (i % 18) << 3;
            *(uint4*)&B_s[n * EKP + k8] = *(const uint4*)&Bw[n * 144 + k8];
        }
    };

    uint32_t aB = smem_u32(A_s) + ((uint32_t)((lr0 - g + (lane & 15)) * EKP + ((lane >> 4) << 3)) << 1);
    uint32_t bB = smem_u32(B_s) + ((uint32_t)(((lane & 7) + ((lane & 16) >> 1)) * EKP) << 1) + ((lane & 8) << 1);

    // ---- stage h + f-columns; stage B0
    stageA(g_h);
    if (tid & 1) {
        int row = row0 + srr;
        int b = row / NNODE, n = row - b * NNODE;
        const float* xr = x + ((size_t)(b * TSTEPS + t) * NNODE + n) * 2;
        float fa[8] = {xr[0], xr[1], 0.f, 0.f, 0.f, 0.f, 1.f, 0.f};
        if (row < NNODE) {
            fa[2] = g_X1[row * 2]; fa[3] = g_X1[row * 2 + 1];
            fa[4] = g_X2[row * 2]; fa[5] = g_X2[row * 2 + 1];
        }
        *(uint4*)&A_s[srr * EKP + 128] = cvt8h(fa);
        float fz[8] = {0.f, 0.f, 0.f, 0.f, 0.f, 0.f, 0.f, 0.f};
        *(uint4*)&A_s[srr * EKP + 136] = cvt8h(fz);
    }
    stageB(0);
    __syncthreads();

    // ---- GEMM1: hc = [h|f,1] @ Bext0^T  (b2 folded at k=134)
    float hca[2][8][4];
#pragma unroll
    for (int c = 0; c < 2; c++)
#pragma unroll
        for (int i = 0; i < 8; i++)
#pragma unroll
            for (int j = 0; j < 4; j++) hca[c][i][j] = 0.f;
    do_gemm<9>(hca, aB, bB);

    if (corr) {
        __syncthreads();
        stageAg(g_P1);
        stageB(1);
        __syncthreads();
        do_gemm<8>(hca, aB, bB);
        __syncthreads();
        stageAg(g_P2);
        stageB(2);
        __syncthreads();
        do_gemm<8>(hca, aB, bB);
    }

    // ---- write hc -> A_s cols 0..127 (f columns persist); stage Bz
    __syncthreads();
#pragma unroll
    for (int ch = 0; ch < 2; ch++)
#pragma unroll
        for (int nt = 0; nt < 8; nt++) {
            int c = ch * 64 + nt * 8 + q;
            *(__half2*)&A_s[lr0 * EKP + c] = __floats2half2_rn(hca[ch][nt][0], hca[ch][nt][1]);
            *(__half2*)&A_s[lr1 * EKP + c] = __floats2half2_rn(hca[ch][nt][2], hca[ch][nt][3]);
        }
    stageB(3);
    __syncthreads();

    // ---- GEMM-z: sigmoid only, z packed fp16 in regs
    uint32_t zp[2][8][2];
    {
        float acc[2][8][4];
#pragma unroll
        for (int c = 0; c < 2; c++)
#pragma unroll
            for (int i = 0; i < 8; i++)
#pragma unroll
                for (int j = 0; j < 4; j++) acc[c][i][j] = 0.f;
        do_gemm<9>(acc, aB, bB);
#pragma unroll
        for (int ch = 0; ch < 2; ch++)
#pragma unroll
            for (int nt = 0; nt < 8; nt++)
#pragma unroll
                for (int hh = 0; hh < 2; hh++) {
                    __half2 zh = __floats2half2_rn(fsig(acc[ch][nt][hh * 2]), fsig(acc[ch][nt][hh * 2 + 1]));
                    zp[ch][nt][hh] = *(uint32_t*)&zh;
                }
    }
    __syncthreads();
    stageB(4);
    __syncthreads();

    // ---- GEMM-r: sigmoid, multiply into A_s (hc) in place
    {
        float acc[2][8][4];
#pragma unroll
        for (int c = 0; c < 2; c++)
#pragma unroll
            for (int i = 0; i < 8; i++)
#pragma unroll
                for (int j = 0; j < 4; j++) acc[c][i][j] = 0.f;
        do_gemm<9>(acc, aB, bB);
#pragma unroll
        for (int ch = 0; ch < 2; ch++)
#pragma unroll
            for (int nt = 0; nt < 8; nt++)
#pragma unroll
                for (int j = 0; j < 4; j++)
                    acc[ch][nt][j] = fsig(acc[ch][nt][j]);
        __syncthreads();   // all warps done reading A_s via ldsm
#pragma unroll
        for (int ch = 0; ch < 2; ch++)
#pragma unroll
            for (int nt = 0; nt < 8; nt++) {
                int c = ch * 64 + nt * 8 + q;
#pragma unroll
                for (int hh = 0; hh < 2; hh++) {
                    int lrow = hh ? lr1 : lr0;
                    __half2* hp = (__half2*)&A_s[lrow * EKP + c];
                    __half2 rv = __floats2half2_rn(acc[ch][nt][hh * 2], acc[ch][nt][hh * 2 + 1]);
                    *hp = __hmul2(*hp, rv);
                }
            }
    }
    stageB(5);
    __syncthreads();

    // ---- GEMM3: candidate + GRU update -> g_h
    {
        float acc[2][8][4];
#pragma unroll
        for (int c = 0; c < 2; c++)
#pragma unroll
            for (int i = 0; i < 8; i++)
#pragma unroll
                for (int j = 0; j < 4; j++) acc[c][i][j] = 0.f;
        do_gemm<9>(acc, aB, bB);
#pragma unroll
        for (int ch = 0; ch < 2; ch++)
#pragma unroll
            for (int nt = 0; nt < 8; nt++) {
                int c = ch * 64 + nt * 8 + q;
#pragma unroll
                for (int hh = 0; hh < 2; hh++) {
                    int grow = row0 + (hh ? lr1 : lr0);
                    float t0 = ftanh(acc[ch][nt][hh * 2]);
                    float t1 = ftanh(acc[ch][nt][hh * 2 + 1]);
                    float2 zv = __half22float2(*(__half2*)&zp[ch][nt][hh]);
                    float2 hp = *(float2*)&g_h[(size_t)grow * 128 + c];
                    float2 o;
                    o.x = zv.x * hp.x + (1.f - zv.x) * t0;
                    o.y = zv.y * hp.y + (1.f - zv.y) * t1;
                    *(float2*)&g_h[(size_t)grow * 128 + c] = o;
                }
            }
    }
}

// ---------------- output head ----------------
__global__ void out_kernel(const float* __restrict__ Wo, const float* __restrict__ bo,
                           float* __restrict__ out) {
    int idx = blockIdx.x * blockDim.x + threadIdx.x;
    if (idx >= NTOT * HORZ) return;
    int i = idx / HORZ, hor = idx - i * HORZ;
    const float* hr = g_h + (size_t)i * HD;
    float s = bo[hor];
#pragma unroll 8
    for (int k = 0; k < HD; k++) s = fmaf(hr[k], Wo[k * HORZ + hor], s);
    int b = i / NNODE, n = i - b * NNODE;
    out[(size_t)(b * HORZ + hor) * NNODE + n] = s;
}

// ---------------- launch ----------------
extern "C" void kernel_launch(void* const* d_in, const int* in_sizes, int n_in,
                              void* d_out, int out_size) {
    const float* x  = (const float*)d_in[0];
    const void*  ei = d_in[1];
    const float* W1 = (const float*)d_in[2];
    const float* b1 = (const float*)d_in[3];
    const float* W2 = (const float*)d_in[4];
    const float* b2 = (const float*)d_in[5];
    const float* Wz = (const float*)d_in[6];
    const float* bz = (const float*)d_in[7];
    const float* Wr = (const float*)d_in[8];
    const float* br = (const float*)d_in[9];
    const float* Wc = (const float*)d_in[10];
    const float* bc = (const float*)d_in[11];
    const float* Wo = (const float*)d_in[12];
    const float* bo = (const float*)d_in[13];
    float* out = (float*)d_out;
    (void)in_sizes; (void)n_in; (void)out_size;

    const int SMEM = 2 * 128 * EKP * 2;   // 77824
    cudaFuncSetAttribute(cell_kernel, cudaFuncAttributeMaxDynamicSharedMemorySize, SMEM);

    zero_h_kernel<<<(NTOT * HD + 1023) / 1024, 1024>>>();
    zero_counts_kernel<<<(2 * NNODE + 255) / 256, 256>>>();
    detect_dtype_kernel<<<(2 * NEDGE + 255) / 256, 256>>>(ei);
    set_is64_kernel<<<1, 1>>>();
    count_edges_kernel<<<(NEDGE + 255) / 256, 256>>>(ei);
    norm_kernel<<<(NEDGE + 255) / 256, 256>>>(ei);
    scan_kernel<<<1, 1024>>>();
    fill_kernel<<<(NEDGE + 255) / 256, 256>>>(ei);
    build_zr_fold_kernel<<<(7 * 256 + 255) / 256, 256>>>(W1, b1, Wz, bz, Wr, br);
    build_c_fold_kernel<<<(7 * HD + 255) / 256, 256>>>(W1, b1, Wc, bc);
    build_bext_kernel<<<(6 * 128 * 144 + 255) / 256, 256>>>(W2, Wz, Wr, Wc, b2);

    for (int t = 0; t < TSTEPS; t++) {
        const float* xt0 = x + (size_t)t * NNODE * INF;   // batch 0, timestep t
        prop_kernel<<<NNODE, HD>>>(0, xt0);
        prop_kernel<<<NNODE, HD>>>(1, nullptr);
        cell_kernel<<<NTOT / 128, 256, SMEM>>>(x, t);
    }

    out_kernel<<<(NTOT * HORZ + 255) / 256, 256>>>(Wo, bo, out);
}